// round 1
// baseline (speedup 1.0000x reference)
#include <cuda_runtime.h>
#include <cuda_bf16.h>

#define IMG_S   4096
#define N_DOTS  100
#define TILE    32
#define NTHREADS 256

// Each block renders a 32x32 tile. Thread t handles 4 consecutive x-pixels
// (float4 lane) of one row: x = tx0 + (t&7)*4, y = ty0 + (t>>3).
__global__ __launch_bounds__(NTHREADS)
void PatchTrainer_dots_kernel(const float* __restrict__ patch,
                              const float* __restrict__ centers,
                              const float* __restrict__ radii,
                              const float* __restrict__ colors,
                              float* __restrict__ out) {
    __shared__ float sxc[N_DOTS];
    __shared__ float syc[N_DOTS];
    __shared__ float sr2[N_DOTS];
    __shared__ float scol[N_DOTS * 3];
    __shared__ int   slist[N_DOTS];
    __shared__ int   scount;

    const int tid = threadIdx.x;
    if (tid == 0) scount = 0;

    // Load colors into shared
    for (int i = tid; i < N_DOTS * 3; i += NTHREADS) scol[i] = colors[i];

    const int tx0 = blockIdx.x * TILE;
    const int ty0 = blockIdx.y * TILE;

    // Transform dot params (match reference f32 math: floor(c*S), floor(r*(S/5)))
    if (tid < N_DOTS) {
        float cx = centers[2 * tid + 0];
        float cy = centers[2 * tid + 1];
        float xc = floorf(__fmul_rn(cx, 4096.0f));
        float yc = floorf(__fmul_rn(cy, 4096.0f));
        float r  = floorf(__fmul_rn(radii[tid], 819.2f)); // f32(4096/5)
        sxc[tid] = xc;
        syc[tid] = yc;
        sr2[tid] = __fmul_rn(r, r);
    }
    __syncthreads();

    // Cull: does circle intersect this tile's pixel rect?
    if (tid < N_DOTS) {
        float xc = sxc[tid], yc = syc[tid], r2 = sr2[tid];
        float px = fminf(fmaxf(xc, (float)tx0), (float)(tx0 + TILE - 1));
        float py = fminf(fmaxf(yc, (float)ty0), (float)(ty0 + TILE - 1));
        float dx = xc - px, dy = yc - py;
        if (dx * dx + dy * dy <= r2) {
            int slot = atomicAdd(&scount, 1);
            slist[slot] = tid;
        }
    }
    __syncthreads();
    const int cnt = scount;

    const int x = tx0 + ((tid & 7) << 2);
    const int y = ty0 + (tid >> 3);
    const float yf  = (float)y;
    const float x0f = (float)x;

    int best0 = -1, best1 = -1, best2 = -1, best3 = -1;

    for (int k = 0; k < cnt; ++k) {
        const int   d  = slist[k];
        const float xc = sxc[d];
        const float yc = syc[d];
        const float r2 = sr2[d];

        // dy, dx are exact integers in f32 (|v| < 2^24); only the final add
        // rounds — matching the reference's (x-xc)^2 + (y-yc)^2 in f32.
        float dy  = __fadd_rn(yf, -yc);
        float dy2 = __fmul_rn(dy, dy);
        float dx0 = __fadd_rn(x0f, -xc);
        float dx1 = dx0 + 1.0f;   // exact
        float dx2 = dx0 + 2.0f;   // exact
        float dx3 = dx0 + 3.0f;   // exact

        float d20 = __fadd_rn(__fmul_rn(dx0, dx0), dy2);
        float d21 = __fadd_rn(__fmul_rn(dx1, dx1), dy2);
        float d22 = __fadd_rn(__fmul_rn(dx2, dx2), dy2);
        float d23 = __fadd_rn(__fmul_rn(dx3, dx3), dy2);

        if (d20 <= r2) best0 = max(best0, d);
        if (d21 <= r2) best1 = max(best1, d);
        if (d22 <= r2) best2 = max(best2, d);
        if (d23 <= r2) best3 = max(best3, d);
    }

    const size_t pix   = (size_t)y * IMG_S + (size_t)x;
    const size_t plane = (size_t)IMG_S * IMG_S;
    const bool need_in = (best0 < 0) | (best1 < 0) | (best2 < 0) | (best3 < 0);

#pragma unroll
    for (int c = 0; c < 3; ++c) {
        float4 v = make_float4(0.f, 0.f, 0.f, 0.f);
        if (need_in) {
            v = *reinterpret_cast<const float4*>(patch + c * plane + pix);
        }
        float4 o;
        o.x = (best0 >= 0) ? scol[best0 * 3 + c] : v.x;
        o.y = (best1 >= 0) ? scol[best1 * 3 + c] : v.y;
        o.z = (best2 >= 0) ? scol[best2 * 3 + c] : v.z;
        o.w = (best3 >= 0) ? scol[best3 * 3 + c] : v.w;
        *reinterpret_cast<float4*>(out + c * plane + pix) = o;
    }
}

extern "C" void kernel_launch(void* const* d_in, const int* in_sizes, int n_in,
                              void* d_out, int out_size) {
    const float* adv_patch = (const float*)d_in[0];
    const float* centers   = (const float*)d_in[1];
    const float* radii     = (const float*)d_in[2];
    const float* colors    = (const float*)d_in[3];
    float* out = (float*)d_out;

    dim3 grid(IMG_S / TILE, IMG_S / TILE);  // 128 x 128 tiles
    PatchTrainer_dots_kernel<<<grid, NTHREADS>>>(adv_patch, centers, radii,
                                                 colors, out);
}

// round 2
// speedup vs baseline: 1.3595x; 1.3595x over previous
#include <cuda_runtime.h>
#include <cuda_bf16.h>

#define IMG_S   4096
#define N_DOTS  100
#define TILE    32
#define NTHREADS 256

// Each block renders a 32x32 tile. Thread t handles 4 consecutive x-pixels
// (one float4) of one row: x = tx0 + (t&7)*4, y = ty0 + (t>>3).
__global__ __launch_bounds__(NTHREADS)
void PatchTrainer_dots_kernel(const float* __restrict__ patch,
                              const float* __restrict__ centers,
                              const float* __restrict__ radii,
                              const float* __restrict__ colors,
                              float* __restrict__ out) {
    __shared__ float    sxc[N_DOTS];
    __shared__ float    syc[N_DOTS];
    __shared__ float    sr2[N_DOTS];
    __shared__ float    scol[N_DOTS * 3];
    __shared__ unsigned s_inter[4];    // intersect ballot, dots 0..127
    __shared__ unsigned s_cont[4];     // fully-contains ballot
    __shared__ int      slist[N_DOTS]; // descending dot indices
    __shared__ int      scount;
    __shared__ int      sfull;         // last list entry fully contains tile

    const int tid  = threadIdx.x;
    const int tx0  = blockIdx.x * TILE;
    const int ty0  = blockIdx.y * TILE;

    for (int i = tid; i < N_DOTS * 3; i += NTHREADS) scol[i] = colors[i];

    // ---- transform + cull (dots 0..99 on threads 0..99) ----
    bool inter = false, cont = false;
    if (tid < N_DOTS) {
        float xc = floorf(__fmul_rn(centers[2 * tid + 0], 4096.0f));
        float yc = floorf(__fmul_rn(centers[2 * tid + 1], 4096.0f));
        float r  = floorf(__fmul_rn(radii[tid], 819.2f));
        float r2 = __fmul_rn(r, r);
        sxc[tid] = xc; syc[tid] = yc; sr2[tid] = r2;

        // Intersect: nearest pixel of tile rect, with the reference rounding
        // chain rn(rn(dx*dx)+rn(dy*dy)) so we never miss a covered pixel.
        float nx = fminf(fmaxf(xc, (float)tx0), (float)(tx0 + TILE - 1));
        float ny = fminf(fmaxf(yc, (float)ty0), (float)(ty0 + TILE - 1));
        float ndx = __fadd_rn(nx, -xc), ndy = __fadd_rn(ny, -yc);
        inter = __fadd_rn(__fmul_rn(ndx, ndx), __fmul_rn(ndy, ndy)) <= r2;

        // Contains: farthest |dx|,|dy| combo, same rounding chain. Monotone
        // rounding => every interior pixel's reference d2 <= this => safe.
        float ax = fmaxf(fabsf(__fadd_rn((float)tx0, -xc)),
                         fabsf(__fadd_rn((float)(tx0 + TILE - 1), -xc)));
        float ay = fmaxf(fabsf(__fadd_rn((float)ty0, -yc)),
                         fabsf(__fadd_rn((float)(ty0 + TILE - 1), -yc)));
        cont = __fadd_rn(__fmul_rn(ax, ax), __fmul_rn(ay, ay)) <= r2;
    }
    unsigned bi = __ballot_sync(0xffffffffu, inter);
    unsigned bc = __ballot_sync(0xffffffffu, cont);
    if ((tid & 31) == 0 && tid < 128) {
        s_inter[tid >> 5] = bi;
        s_cont[tid >> 5]  = bc;
    }
    __syncthreads();

    // ---- thread 0: descending list, truncated at highest containing dot ----
    if (tid == 0) {
        int base = -1;
        #pragma unroll
        for (int w = 3; w >= 0; --w) {
            unsigned m = s_cont[w];
            if (base < 0 && m) base = (w << 5) + 31 - __clz(m);
        }
        int cnt = 0;
        for (int w = 3; w >= 0; --w) {
            unsigned m = s_inter[w];
            while (m) {
                int b = 31 - __clz(m);
                m &= ~(1u << b);
                int d = (w << 5) + b;
                if (base >= 0 && d < base) { m = 0; break; }
                slist[cnt++] = d;
                if (d == base) { m = 0; break; }
            }
            if (base >= 0 && cnt > 0 && slist[cnt - 1] == base) break;
        }
        scount = cnt;
        sfull  = (base >= 0);
    }
    __syncthreads();

    const int  cnt  = scount;
    const bool full = (sfull != 0);

    const int x = tx0 + ((tid & 7) << 2);
    const int y = ty0 + (tid >> 3);
    const size_t pix   = (size_t)y * IMG_S + (size_t)x;
    const size_t plane = (size_t)IMG_S * IMG_S;

    // ---- fast path: tile is a single solid color ----
    if (full && cnt == 1) {
        const int d = slist[0];
        #pragma unroll
        for (int c = 0; c < 3; ++c) {
            float col = scol[d * 3 + c];
            float4 o = make_float4(col, col, col, col);
            __stcs(reinterpret_cast<float4*>(out + c * plane + pix), o);
        }
        return;
    }

    const float yf  = (float)y;
    const float x0f = (float)x;

    int best0 = -1, best1 = -1, best2 = -1, best3 = -1;
    unsigned und = 0xFu;

    // ---- descending loop: first covering dot wins, warp-wide early exit ----
    for (int k = 0; k < cnt; ++k) {
        const int   d  = slist[k];
        const float xc = sxc[d];
        const float yc = syc[d];
        const float r2 = sr2[d];

        float dy  = __fadd_rn(yf, -yc);
        float dy2 = __fmul_rn(dy, dy);
        float dx0 = __fadd_rn(x0f, -xc);
        float dx1 = dx0 + 1.0f;  // exact (integers in f32)
        float dx2 = dx0 + 2.0f;
        float dx3 = dx0 + 3.0f;

        if ((und & 1u) && __fadd_rn(__fmul_rn(dx0, dx0), dy2) <= r2) { best0 = d; und &= ~1u; }
        if ((und & 2u) && __fadd_rn(__fmul_rn(dx1, dx1), dy2) <= r2) { best1 = d; und &= ~2u; }
        if ((und & 4u) && __fadd_rn(__fmul_rn(dx2, dx2), dy2) <= r2) { best2 = d; und &= ~4u; }
        if ((und & 8u) && __fadd_rn(__fmul_rn(dx3, dx3), dy2) <= r2) { best3 = d; und &= ~8u; }

        if (__all_sync(0xffffffffu, und == 0u)) break;
    }

    #pragma unroll
    for (int c = 0; c < 3; ++c) {
        float4 v = make_float4(0.f, 0.f, 0.f, 0.f);
        if (und != 0u) {
            v = *reinterpret_cast<const float4*>(patch + c * plane + pix);
        }
        float4 o;
        o.x = (best0 >= 0) ? scol[best0 * 3 + c] : v.x;
        o.y = (best1 >= 0) ? scol[best1 * 3 + c] : v.y;
        o.z = (best2 >= 0) ? scol[best2 * 3 + c] : v.z;
        o.w = (best3 >= 0) ? scol[best3 * 3 + c] : v.w;
        __stcs(reinterpret_cast<float4*>(out + c * plane + pix), o);
    }
}

extern "C" void kernel_launch(void* const* d_in, const int* in_sizes, int n_in,
                              void* d_out, int out_size) {
    const float* adv_patch = (const float*)d_in[0];
    const float* centers   = (const float*)d_in[1];
    const float* radii     = (const float*)d_in[2];
    const float* colors    = (const float*)d_in[3];
    float* out = (float*)d_out;

    dim3 grid(IMG_S / TILE, IMG_S / TILE);  // 128 x 128 tiles
    PatchTrainer_dots_kernel<<<grid, NTHREADS>>>(adv_patch, centers, radii,
                                                 colors, out);
}

// round 3
// speedup vs baseline: 1.3752x; 1.0116x over previous
#include <cuda_runtime.h>
#include <cuda_bf16.h>

#define IMG_S   4096
#define N_DOTS  100
#define TW      64
#define TH      32
#define NTHREADS 256

// Block = 64x32 tile. Thread t: row y = ty0 + (t>>3), x0 = tx0 + (t&7)*4,
// handles two float4 quads at x0 and x0+32 (same row -> shared dy^2).
__global__ __launch_bounds__(NTHREADS)
void PatchTrainer_dots_kernel(const float* __restrict__ patch,
                              const float* __restrict__ centers,
                              const float* __restrict__ radii,
                              const float* __restrict__ colors,
                              float* __restrict__ out) {
    __shared__ float4   sdot[N_DOTS];   // (xc, yc, r2, idx) descending, truncated
    __shared__ float4   scol4[N_DOTS];  // (r, g, b, 0)
    __shared__ unsigned s_inter[4];
    __shared__ unsigned s_cont[4];

    const int tid = threadIdx.x;
    const int tx0 = blockIdx.x * TW;
    const int ty0 = blockIdx.y * TH;

    // ---- transform + cull: thread d < 100 owns dot d ----
    float xc = 0.f, yc = 0.f, r2 = 0.f;
    bool inter = false, cont = false;
    if (tid < N_DOTS) {
        xc = floorf(__fmul_rn(centers[2 * tid + 0], 4096.0f));
        yc = floorf(__fmul_rn(centers[2 * tid + 1], 4096.0f));
        float r = floorf(__fmul_rn(radii[tid], 819.2f));
        r2 = __fmul_rn(r, r);
        scol4[tid] = make_float4(colors[3 * tid], colors[3 * tid + 1],
                                 colors[3 * tid + 2], 0.f);

        // Intersect: nearest tile pixel, reference rounding chain (never
        // misses a covered pixel; monotone rounding).
        float nx = fminf(fmaxf(xc, (float)tx0), (float)(tx0 + TW - 1));
        float ny = fminf(fmaxf(yc, (float)ty0), (float)(ty0 + TH - 1));
        float ndx = __fadd_rn(nx, -xc), ndy = __fadd_rn(ny, -yc);
        inter = __fadd_rn(__fmul_rn(ndx, ndx), __fmul_rn(ndy, ndy)) <= r2;

        // Contains: farthest corner |dx|,|dy|, same rounding chain.
        float ax = fmaxf(fabsf(__fadd_rn((float)tx0, -xc)),
                         fabsf(__fadd_rn((float)(tx0 + TW - 1), -xc)));
        float ay = fmaxf(fabsf(__fadd_rn((float)ty0, -yc)),
                         fabsf(__fadd_rn((float)(ty0 + TH - 1), -yc)));
        cont = __fadd_rn(__fmul_rn(ax, ax), __fmul_rn(ay, ay)) <= r2;
    }
    unsigned bi = __ballot_sync(0xffffffffu, inter);
    unsigned bc = __ballot_sync(0xffffffffu, cont);
    if ((tid & 31) == 0 && tid < 128) {
        s_inter[tid >> 5] = bi;
        s_cont[tid >> 5]  = bc;
    }
    __syncthreads();

    // ---- every thread: base (highest containing dot) + eligible masks ----
    const unsigned cw0 = s_cont[0], cw1 = s_cont[1], cw2 = s_cont[2], cw3 = s_cont[3];
    int base = -1;
    if      (cw3) base = 96 + 31 - __clz(cw3);
    else if (cw2) base = 64 + 31 - __clz(cw2);
    else if (cw1) base = 32 + 31 - __clz(cw1);
    else if (cw0) base =      31 - __clz(cw0);

    unsigned e0 = s_inter[0], e1 = s_inter[1], e2 = s_inter[2], e3 = s_inter[3];
    if (base >= 0) {
        const int bw = base >> 5;
        const unsigned keep = 0xffffffffu << (base & 31);
        if      (bw == 0) { e0 &= keep; }
        else if (bw == 1) { e0 = 0; e1 &= keep; }
        else if (bw == 2) { e0 = 0; e1 = 0; e2 &= keep; }
        else              { e0 = 0; e1 = 0; e2 = 0; e3 &= keep; }
    }
    const int cnt = __popc(e0) + __popc(e1) + __popc(e2) + __popc(e3);

    // ---- parallel compaction into descending list ----
    if (tid < N_DOTS && inter && (base < 0 || tid >= base)) {
        const int w = tid >> 5, b = tid & 31;
        const unsigned own = (w == 0) ? e0 : (w == 1) ? e1 : (w == 2) ? e2 : e3;
        int rank = __popc(own & (0xFFFFFFFEu << b));  // eligible above me in word
        if (w < 1) rank += __popc(e1);
        if (w < 2) rank += __popc(e2);
        if (w < 3) rank += __popc(e3);
        sdot[rank] = make_float4(xc, yc, r2, __int_as_float(tid));
    }
    __syncthreads();

    const int x = tx0 + ((tid & 7) << 2);
    const int y = ty0 + (tid >> 3);
    const size_t pix   = (size_t)y * IMG_S + (size_t)x;
    const size_t plane = (size_t)IMG_S * IMG_S;

    // ---- fast path: solid tile ----
    if (base >= 0 && cnt == 1) {
        const float4 cc = scol4[base];
        #pragma unroll
        for (int c = 0; c < 3; ++c) {
            const float col = (c == 0) ? cc.x : (c == 1) ? cc.y : cc.z;
            const float4 o = make_float4(col, col, col, col);
            __stcs(reinterpret_cast<float4*>(out + c * plane + pix),      o);
            __stcs(reinterpret_cast<float4*>(out + c * plane + pix + 32), o);
        }
        return;
    }

    // ---- fast path: untouched tile (pure copy) ----
    if (cnt == 0) {
        #pragma unroll
        for (int c = 0; c < 3; ++c) {
            float4 a = *reinterpret_cast<const float4*>(patch + c * plane + pix);
            float4 b = *reinterpret_cast<const float4*>(patch + c * plane + pix + 32);
            __stcs(reinterpret_cast<float4*>(out + c * plane + pix),      a);
            __stcs(reinterpret_cast<float4*>(out + c * plane + pix + 32), b);
        }
        return;
    }

    // ---- per-pixel descending loop over compacted list ----
    const float yf  = (float)y;
    const float x0f = (float)x;

    int b0 = -1, b1 = -1, b2 = -1, b3 = -1, b4 = -1, b5 = -1, b6 = -1, b7 = -1;

    for (int k = 0; k < cnt; ++k) {
        const float4 dv = sdot[k];
        const int    d  = __float_as_int(dv.w);

        const float dy  = __fadd_rn(yf, -dv.y);
        const float dy2 = __fmul_rn(dy, dy);
        const float dx0 = __fadd_rn(x0f, -dv.x);
        // exact integer offsets in f32
        const float dx1 = dx0 + 1.0f,  dx2 = dx0 + 2.0f,  dx3 = dx0 + 3.0f;
        const float dx4 = dx0 + 32.0f, dx5 = dx0 + 33.0f, dx6 = dx0 + 34.0f, dx7 = dx0 + 35.0f;

        if (b0 < 0 && __fadd_rn(__fmul_rn(dx0, dx0), dy2) <= dv.z) b0 = d;
        if (b1 < 0 && __fadd_rn(__fmul_rn(dx1, dx1), dy2) <= dv.z) b1 = d;
        if (b2 < 0 && __fadd_rn(__fmul_rn(dx2, dx2), dy2) <= dv.z) b2 = d;
        if (b3 < 0 && __fadd_rn(__fmul_rn(dx3, dx3), dy2) <= dv.z) b3 = d;
        if (b4 < 0 && __fadd_rn(__fmul_rn(dx4, dx4), dy2) <= dv.z) b4 = d;
        if (b5 < 0 && __fadd_rn(__fmul_rn(dx5, dx5), dy2) <= dv.z) b5 = d;
        if (b6 < 0 && __fadd_rn(__fmul_rn(dx6, dx6), dy2) <= dv.z) b6 = d;
        if (b7 < 0 && __fadd_rn(__fmul_rn(dx7, dx7), dy2) <= dv.z) b7 = d;

        const int mn = min(min(min(b0, b1), min(b2, b3)),
                           min(min(b4, b5), min(b6, b7)));
        if (__all_sync(0xffffffffu, mn >= 0)) break;
    }

    // ---- emit: per-pixel color via one LDS.128, input only where uncovered ----
    const float4 c0 = scol4[max(b0, 0)];
    const float4 c1 = scol4[max(b1, 0)];
    const float4 c2 = scol4[max(b2, 0)];
    const float4 c3 = scol4[max(b3, 0)];
    const float4 c4 = scol4[max(b4, 0)];
    const float4 c5 = scol4[max(b5, 0)];
    const float4 c6 = scol4[max(b6, 0)];
    const float4 c7 = scol4[max(b7, 0)];

    const bool lo_in = (b0 < 0) | (b1 < 0) | (b2 < 0) | (b3 < 0);
    const bool hi_in = (b4 < 0) | (b5 < 0) | (b6 < 0) | (b7 < 0);

    #pragma unroll
    for (int c = 0; c < 3; ++c) {
        float4 vlo = make_float4(0.f, 0.f, 0.f, 0.f);
        float4 vhi = make_float4(0.f, 0.f, 0.f, 0.f);
        if (lo_in) vlo = *reinterpret_cast<const float4*>(patch + c * plane + pix);
        if (hi_in) vhi = *reinterpret_cast<const float4*>(patch + c * plane + pix + 32);

        float4 o, p;
        o.x = (b0 >= 0) ? ((c == 0) ? c0.x : (c == 1) ? c0.y : c0.z) : vlo.x;
        o.y = (b1 >= 0) ? ((c == 0) ? c1.x : (c == 1) ? c1.y : c1.z) : vlo.y;
        o.z = (b2 >= 0) ? ((c == 0) ? c2.x : (c == 1) ? c2.y : c2.z) : vlo.z;
        o.w = (b3 >= 0) ? ((c == 0) ? c3.x : (c == 1) ? c3.y : c3.z) : vlo.w;
        p.x = (b4 >= 0) ? ((c == 0) ? c4.x : (c == 1) ? c4.y : c4.z) : vhi.x;
        p.y = (b5 >= 0) ? ((c == 0) ? c5.x : (c == 1) ? c5.y : c5.z) : vhi.y;
        p.z = (b6 >= 0) ? ((c == 0) ? c6.x : (c == 1) ? c6.y : c6.z) : vhi.z;
        p.w = (b7 >= 0) ? ((c == 0) ? c7.x : (c == 1) ? c7.y : c7.z) : vhi.w;

        __stcs(reinterpret_cast<float4*>(out + c * plane + pix),      o);
        __stcs(reinterpret_cast<float4*>(out + c * plane + pix + 32), p);
    }
}

extern "C" void kernel_launch(void* const* d_in, const int* in_sizes, int n_in,
                              void* d_out, int out_size) {
    const float* adv_patch = (const float*)d_in[0];
    const float* centers   = (const float*)d_in[1];
    const float* radii     = (const float*)d_in[2];
    const float* colors    = (const float*)d_in[3];
    float* out = (float*)d_out;

    dim3 grid(IMG_S / TW, IMG_S / TH);  // 64 x 128 = 8192 blocks
    PatchTrainer_dots_kernel<<<grid, NTHREADS>>>(adv_patch, centers, radii,
                                                 colors, out);
}